// round 4
// baseline (speedup 1.0000x reference)
#include <cuda_runtime.h>
#include <math.h>

#define T_STEPS 1000
#define BATCH   1024
#define IN_DIM  80
#define HID     128
#define OUT_DIM 10

__device__ float g_xw[(size_t)T_STEPS * BATCH * HID];   // 524 MB (BSS)
__device__ float g_coef[T_STEPS];
__device__ float g_wrp[HID * HID];   // permuted w_rec^T (coalesced sim loads)

// ---------------------------------------------------------------------------
// Prep: readout coefficients (closed form c_u = 0.9^(T-u) - 0.8^(T-u)) and
// permuted recurrent weights g_wrp[k*128 + ln*4 + r] = wrec[(r*32+ln)*128+k].
// ---------------------------------------------------------------------------
__global__ void prep_kernel(const float* __restrict__ wrec) {
    int idx = blockIdx.x * blockDim.x + threadIdx.x;
    if (idx < HID * HID) {
        int k = idx >> 7, j = idx & 127;
        int ln = j >> 2, r = j & 3;
        g_wrp[idx] = wrec[(r * 32 + ln) * HID + k];
    }
    if (idx < T_STEPS) {
        double n = (double)(T_STEPS - idx);
        g_coef[idx] = (float)(pow(0.9, n) - pow(0.8, n));
    }
}

// ---------------------------------------------------------------------------
// Packed-fp32 FMA (sm_100+ f32x2): halves are independent IEEE fp32 FMAs —
// bitwise identical to scalar FFMA chains (validated R3: rel_err unchanged).
// ---------------------------------------------------------------------------
__device__ __forceinline__ unsigned long long ffma2(unsigned long long a,
                                                    unsigned long long b,
                                                    unsigned long long c) {
    unsigned long long d;
    asm("fma.rn.f32x2 %0, %1, %2, %3;" : "=l"(d) : "l"(a), "l"(b), "l"(c));
    return d;
}

// ---------------------------------------------------------------------------
// Input GEMM: (T*B,80) @ (80,128) -> g_xw. FFMA2 with zero packing movs:
//  - xsP[k][row]    : x transposed in smem; a row-pair (2p,2p+1) = one LDS.64
//  - ws2[col][k]    : w duplicated {w,w} in smem; one LDS.64
// Inner loop per k: 12x LDS.64 + 32x FFMA2. Per-element ascending-k chain
// bitwise identical to the scalar version. 1 CTA/SM (125 KB smem, no spills).
// ---------------------------------------------------------------------------
#define XP_STR  132   // floats per k-row of xsP (128 + pad)
#define WS2_STR 81    // float2 per col of ws2 (80 + pad; conflict-free)
#define GEMM_SMEM (80 * XP_STR * 4 + HID * WS2_STR * 8)

__global__ __launch_bounds__(256, 1)
void gemm_in(const float* __restrict__ x, const float* __restrict__ w) {
    extern __shared__ float sm[];
    float*  xsP = sm;                            // [80][XP_STR]
    float2* ws2 = (float2*)(sm + 80 * XP_STR);   // [128][WS2_STR]
    int tid = threadIdx.x;
    size_t rowbase = (size_t)blockIdx.x * 128;

    // x tile: 128 rows x 80 -> transposed store
    const float4* xg = (const float4*)(x + rowbase * IN_DIM);
#pragma unroll
    for (int it = 0; it < 10; ++it) {
        int e = tid + it * 256;
        int row = e / 20, c4 = e % 20;
        float4 v = xg[e];
        int k0 = c4 * 4;
        xsP[(k0 + 0) * XP_STR + row] = v.x;
        xsP[(k0 + 1) * XP_STR + row] = v.y;
        xsP[(k0 + 2) * XP_STR + row] = v.z;
        xsP[(k0 + 3) * XP_STR + row] = v.w;
    }
    // w: duplicated pairs
    for (int e = tid; e < HID * IN_DIM; e += 256) {
        float wv = w[e];
        ws2[(e / IN_DIM) * WS2_STR + (e % IN_DIM)] = make_float2(wv, wv);
    }
    __syncthreads();

    int mrow = (tid >> 4) * 8;
    int mcol = tid & 15;

    unsigned long long acc2[4][8];
#pragma unroll
    for (int p = 0; p < 4; p++)
#pragma unroll
        for (int j = 0; j < 8; j++) acc2[p][j] = 0ull;

#pragma unroll 2
    for (int k = 0; k < IN_DIM; ++k) {
        unsigned long long a2[4], b2[8];
        const float* xk = &xsP[k * XP_STR + mrow];
#pragma unroll
        for (int p = 0; p < 4; p++)
            a2[p] = *(const unsigned long long*)(xk + 2 * p);
#pragma unroll
        for (int j = 0; j < 8; j++)
            b2[j] = *(const unsigned long long*)&ws2[(mcol + 16 * j) * WS2_STR + k];
#pragma unroll
        for (int p = 0; p < 4; p++)
#pragma unroll
            for (int j = 0; j < 8; j++)
                acc2[p][j] = ffma2(a2[p], b2[j], acc2[p][j]);
    }

    float* op = g_xw + rowbase * HID;
#pragma unroll
    for (int p = 0; p < 4; p++)
#pragma unroll
        for (int j = 0; j < 8; j++) {
            float lo, hi;
            asm("mov.b64 {%0, %1}, %2;" : "=f"(lo), "=f"(hi) : "l"(acc2[p][j]));
            op[(mrow + 2 * p) * HID + mcol + 16 * j] = lo;
            op[(mrow + 2 * p + 1) * HID + mcol + 16 * j] = hi;
        }
}

// ---------------------------------------------------------------------------
// Persistent simulation. Numerics/order bit-identical to R2/R3. New: spike
// column loads software-pipelined (first load of each mask pre-issued; 1-deep
// pipeline within each mask). Add order remains strictly ascending k.
// ---------------------------------------------------------------------------
#define SIM_SMEM ((HID * HID + T_STEPS + OUT_DIM * HID) * 4)

__global__ __launch_bounds__(256, 1)
void sim_kernel(const float* __restrict__ wout, float* __restrict__ out) {
    extern __shared__ float sm[];
    float* wrp = sm;                 // permuted w_rec^T, 128*128
    float* cf  = wrp + HID * HID;
    float* wo  = cf + T_STEPS;
    int tid = threadIdx.x, lane = tid & 31, wid = tid >> 5;
    int b = blockIdx.x * 8 + wid;

    // coalesced smem fills from prepped gmem
    {
        const float4* s = (const float4*)g_wrp;
        float4* d = (float4*)wrp;
        for (int e = tid; e < HID * HID / 4; e += 256) d[e] = s[e];
    }
    for (int e = tid; e < T_STEPS; e += 256) cf[e] = g_coef[e];
    for (int e = tid; e < OUT_DIM * HID; e += 256) wo[e] = wout[e];
    __syncthreads();

    float v0 = 0.f, v1 = 0.f, v2 = 0.f, v3 = 0.f;
    float i0 = 0.f, i1 = 0.f, i2 = 0.f, i3 = 0.f;
    float a0 = 0.f, a1 = 0.f, a2 = 0.f, a3 = 0.f;

    const float* xwp = g_xw + (size_t)b * HID + lane;
    const size_t tstride = (size_t)BATCH * HID;
    const float4* wr4 = (const float4*)wrp;   // column k: wr4[k*32 + lane]

    float xn0 = __ldg(xwp), xn1 = __ldg(xwp + 32), xn2 = __ldg(xwp + 64),
          xn3 = __ldg(xwp + 96);

    for (int t = 0; t < T_STEPS; ++t) {
        float xc0 = xn0, xc1 = xn1, xc2 = xn2, xc3 = xn3;
        if (t + 1 < T_STEPS) {
            const float* p = xwp + (size_t)(t + 1) * tstride;
            xn0 = __ldg(p); xn1 = __ldg(p + 32); xn2 = __ldg(p + 64);
            xn3 = __ldg(p + 96);
        }
        float ct = cf[t];

        float vd0 = __fadd_rn(v0, __fmul_rn(0.1f, __fadd_rn(__fsub_rn(0.f, v0), i0)));
        float vd1 = __fadd_rn(v1, __fmul_rn(0.1f, __fadd_rn(__fsub_rn(0.f, v1), i1)));
        float vd2 = __fadd_rn(v2, __fmul_rn(0.1f, __fadd_rn(__fsub_rn(0.f, v2), i2)));
        float vd3 = __fadd_rn(v3, __fmul_rn(0.1f, __fadd_rn(__fsub_rn(0.f, v3), i3)));
        float id0 = __fsub_rn(i0, __fmul_rn(0.2f, i0));
        float id1 = __fsub_rn(i1, __fmul_rn(0.2f, i1));
        float id2 = __fsub_rn(i2, __fmul_rn(0.2f, i2));
        float id3 = __fsub_rn(i3, __fmul_rn(0.2f, i3));
        bool z0 = __fsub_rn(vd0, 1.0f) > 0.0f;
        bool z1 = __fsub_rn(vd1, 1.0f) > 0.0f;
        bool z2 = __fsub_rn(vd2, 1.0f) > 0.0f;
        bool z3 = __fsub_rn(vd3, 1.0f) > 0.0f;
        v0 = z0 ? 0.0f : vd0;
        v1 = z1 ? 0.0f : vd1;
        v2 = z2 ? 0.0f : vd2;
        v3 = z3 ? 0.0f : vd3;
        if (z0) a0 = __fadd_rn(a0, ct);
        if (z1) a1 = __fadd_rn(a1, ct);
        if (z2) a2 = __fadd_rn(a2, ct);
        if (z3) a3 = __fadd_rn(a3, ct);

        unsigned m0 = __ballot_sync(0xffffffffu, z0);
        unsigned m1 = __ballot_sync(0xffffffffu, z1);
        unsigned m2 = __ballot_sync(0xffffffffu, z2);
        unsigned m3 = __ballot_sync(0xffffffffu, z3);
        float R0 = 0.f, R1 = 0.f, R2 = 0.f, R3 = 0.f;

        // Pre-issue first column load of each mask (4 independent loads).
        unsigned n0 = m0, n1 = m1, n2 = m2, n3 = m3;
        float4 q0, q1, q2, q3;
        if (n0) { int k = __ffs((int)n0) - 1; n0 &= n0 - 1; q0 = wr4[k * 32 + lane]; }
        if (n1) { int k = __ffs((int)n1) - 1; n1 &= n1 - 1; q1 = wr4[(32 + k) * 32 + lane]; }
        if (n2) { int k = __ffs((int)n2) - 1; n2 &= n2 - 1; q2 = wr4[(64 + k) * 32 + lane]; }
        if (n3) { int k = __ffs((int)n3) - 1; n3 &= n3 - 1; q3 = wr4[(96 + k) * 32 + lane]; }

        // Drain in ascending-k order; 1-deep load pipeline per mask.
        if (m0) {
            while (n0) {
                int k = __ffs((int)n0) - 1; n0 &= n0 - 1;
                float4 qn = wr4[k * 32 + lane];
                R0 = __fadd_rn(R0, q0.x); R1 = __fadd_rn(R1, q0.y);
                R2 = __fadd_rn(R2, q0.z); R3 = __fadd_rn(R3, q0.w);
                q0 = qn;
            }
            R0 = __fadd_rn(R0, q0.x); R1 = __fadd_rn(R1, q0.y);
            R2 = __fadd_rn(R2, q0.z); R3 = __fadd_rn(R3, q0.w);
        }
        if (m1) {
            while (n1) {
                int k = __ffs((int)n1) - 1; n1 &= n1 - 1;
                float4 qn = wr4[(32 + k) * 32 + lane];
                R0 = __fadd_rn(R0, q1.x); R1 = __fadd_rn(R1, q1.y);
                R2 = __fadd_rn(R2, q1.z); R3 = __fadd_rn(R3, q1.w);
                q1 = qn;
            }
            R0 = __fadd_rn(R0, q1.x); R1 = __fadd_rn(R1, q1.y);
            R2 = __fadd_rn(R2, q1.z); R3 = __fadd_rn(R3, q1.w);
        }
        if (m2) {
            while (n2) {
                int k = __ffs((int)n2) - 1; n2 &= n2 - 1;
                float4 qn = wr4[(64 + k) * 32 + lane];
                R0 = __fadd_rn(R0, q2.x); R1 = __fadd_rn(R1, q2.y);
                R2 = __fadd_rn(R2, q2.z); R3 = __fadd_rn(R3, q2.w);
                q2 = qn;
            }
            R0 = __fadd_rn(R0, q2.x); R1 = __fadd_rn(R1, q2.y);
            R2 = __fadd_rn(R2, q2.z); R3 = __fadd_rn(R3, q2.w);
        }
        if (m3) {
            while (n3) {
                int k = __ffs((int)n3) - 1; n3 &= n3 - 1;
                float4 qn = wr4[(96 + k) * 32 + lane];
                R0 = __fadd_rn(R0, q3.x); R1 = __fadd_rn(R1, q3.y);
                R2 = __fadd_rn(R2, q3.z); R3 = __fadd_rn(R3, q3.w);
                q3 = qn;
            }
            R0 = __fadd_rn(R0, q3.x); R1 = __fadd_rn(R1, q3.y);
            R2 = __fadd_rn(R2, q3.z); R3 = __fadd_rn(R3, q3.w);
        }

        i0 = __fadd_rn(__fadd_rn(id0, xc0), R0);
        i1 = __fadd_rn(__fadd_rn(id1, xc1), R1);
        i2 = __fadd_rn(__fadd_rn(id2, xc2), R2);
        i3 = __fadd_rn(__fadd_rn(id3, xc3), R3);
    }

    float vo[OUT_DIM];
#pragma unroll
    for (int o = 0; o < OUT_DIM; ++o) {
        const float* wp = &wo[o * HID];
        float p = a0 * wp[lane] + a1 * wp[32 + lane] + a2 * wp[64 + lane] +
                  a3 * wp[96 + lane];
#pragma unroll
        for (int s = 16; s; s >>= 1) p += __shfl_xor_sync(0xffffffffu, p, s);
        vo[o] = p;
    }
    if (lane == 0) {
        float mx = vo[0];
#pragma unroll
        for (int o = 1; o < OUT_DIM; ++o) mx = fmaxf(mx, vo[o]);
        float se = 0.f;
#pragma unroll
        for (int o = 0; o < OUT_DIM; ++o) se += expf(vo[o] - mx);
        float lse = mx + logf(se);
#pragma unroll
        for (int o = 0; o < OUT_DIM; ++o) out[b * OUT_DIM + o] = vo[o] - lse;
    }
}

extern "C" void kernel_launch(void* const* d_in, const int* in_sizes, int n_in,
                              void* d_out, int out_size) {
    const float* x     = (const float*)d_in[0];
    const float* w_in  = (const float*)d_in[1];
    const float* w_rec = (const float*)d_in[2];
    const float* w_out = (const float*)d_in[3];
    float* out = (float*)d_out;

    cudaFuncSetAttribute(gemm_in, cudaFuncAttributeMaxDynamicSharedMemorySize,
                         GEMM_SMEM);
    cudaFuncSetAttribute(sim_kernel, cudaFuncAttributeMaxDynamicSharedMemorySize,
                         SIM_SMEM);

    prep_kernel<<<64, 256>>>(w_rec);
    gemm_in<<<(T_STEPS * BATCH) / 128, 256, GEMM_SMEM>>>(x, w_in);
    sim_kernel<<<BATCH / 8, 256, SIM_SMEM>>>(w_out, out);
}

// round 5
// speedup vs baseline: 1.1157x; 1.1157x over previous
#include <cuda_runtime.h>
#include <math.h>

#define T_STEPS 1000
#define BATCH   1024
#define IN_DIM  80
#define HID     128
#define OUT_DIM 10

__device__ float g_xw[(size_t)T_STEPS * BATCH * HID];   // 524 MB (BSS)
__device__ float g_coef[T_STEPS];
__device__ float g_wrp[HID * HID];   // pair-permuted w_rec^T

// ---------------------------------------------------------------------------
// Prep: coefficients (closed form c_u = 0.9^(T-u) - 0.8^(T-u)) and permuted
// recurrent weights for the 2-warp-per-element sim:
//   g_wrp[k*128 + half*64 + lane*2 + s] = wrec[(half*2+s)*32 + lane][k]
// so warp `half` fetches its 64-h slice of column k as one LDS.64 float2.
// ---------------------------------------------------------------------------
__global__ void prep_kernel(const float* __restrict__ wrec) {
    int idx = blockIdx.x * blockDim.x + threadIdx.x;
    if (idx < HID * HID) {
        int k = idx >> 7, j = idx & 127;
        int half = j >> 6, lane = (j >> 1) & 31, s = j & 1;
        g_wrp[idx] = wrec[((half * 2 + s) * 32 + lane) * HID + k];
    }
    if (idx < T_STEPS) {
        double n = (double)(T_STEPS - idx);
        g_coef[idx] = (float)(pow(0.9, n) - pow(0.8, n));
    }
}

// ---------------------------------------------------------------------------
// Input GEMM: exact R2 scalar version (known-good: ~91% of fp32 FMA floor,
// bitwise-stable ascending-k chain). DO NOT TOUCH.
// ---------------------------------------------------------------------------
#define XS_STR 84
#define WS_STR 81
#define GEMM_SMEM ((128 * XS_STR + 128 * WS_STR) * 4)

__global__ __launch_bounds__(256, 2)
void gemm_in(const float* __restrict__ x, const float* __restrict__ w) {
    extern __shared__ float sm[];
    float* xs = sm;                 // [128][XS_STR]
    float* ws = sm + 128 * XS_STR;  // [128][WS_STR]
    int tid = threadIdx.x;
    size_t rowbase = (size_t)blockIdx.x * 128;

    const float4* xg = (const float4*)(x + rowbase * IN_DIM);
#pragma unroll
    for (int it = 0; it < 10; ++it) {
        int e = tid + it * 256;
        int row = e / 20, c4 = e % 20;
        float4 v = xg[e];
        *(float4*)&xs[row * XS_STR + c4 * 4] = v;
    }
    for (int e = tid; e < HID * IN_DIM; e += 256)
        ws[(e / IN_DIM) * WS_STR + (e % IN_DIM)] = w[e];
    __syncthreads();

    int mrow = (tid >> 4) * 8;
    int mcol = tid & 15;
    float acc[8][8];
#pragma unroll
    for (int i = 0; i < 8; i++)
#pragma unroll
        for (int j = 0; j < 8; j++) acc[i][j] = 0.f;

#pragma unroll 4
    for (int k = 0; k < IN_DIM; ++k) {
        float a[8], bb[8];
#pragma unroll
        for (int i = 0; i < 8; i++) a[i] = xs[(mrow + i) * XS_STR + k];
#pragma unroll
        for (int j = 0; j < 8; j++) bb[j] = ws[(mcol + 16 * j) * WS_STR + k];
#pragma unroll
        for (int i = 0; i < 8; i++)
#pragma unroll
            for (int j = 0; j < 8; j++)
                acc[i][j] = fmaf(a[i], bb[j], acc[i][j]);
    }

    float* op = g_xw + rowbase * HID;
#pragma unroll
    for (int i = 0; i < 8; i++)
#pragma unroll
        for (int j = 0; j < 8; j++)
            op[(mrow + i) * HID + mcol + 16 * j] = acc[i][j];
}

// ---------------------------------------------------------------------------
// Simulation: 2 warps per batch element (warp pair), each owning 64 h:
//   warp half h = {half*64 + lane, half*64 + 32 + lane}  (s = 0,1)
// Per step: local state update -> 2 ballots -> mask exchange (double-buffered
// 16B smem slot + pairwise named barrier) -> drain all 4 masks ascending-k
// with LDS.64 column slices, packed add.rn.f32x2 (independent IEEE halves).
// Numeric op order identical to R2 (rel_err must stay 6.043687e-4).
// CTA = 256 threads = 4 elements; grid = 256 CTAs; 2 CTAs/SM -> 4 warps/SMSP.
// ---------------------------------------------------------------------------
#define SIM_FLOATS (HID * HID + 32 + T_STEPS + OUT_DIM * HID + 8 * OUT_DIM)
#define SIM_SMEM (SIM_FLOATS * 4)

__global__ __launch_bounds__(256)
void sim_kernel(const float* __restrict__ wout, float* __restrict__ out) {
    extern __shared__ float sm[];
    float* wrp = sm;                           // [16384]
    unsigned* msk = (unsigned*)(wrp + HID * HID);  // [4 pairs][2 bufs][4]
    float* cf  = (float*)(msk + 32);           // [1000]
    float* wo  = cf + T_STEPS;                 // [10][128]
    float* part = wo + OUT_DIM * HID;          // [8 warps][10]
    int tid = threadIdx.x, lane = tid & 31, wid = tid >> 5;
    int pair = wid >> 1, half = wid & 1;
    int e = blockIdx.x * 4 + pair;

    {
        const float4* s4 = (const float4*)g_wrp;
        float4* d4 = (float4*)wrp;
        for (int i = tid; i < HID * HID / 4; i += 256) d4[i] = s4[i];
    }
    for (int i = tid; i < T_STEPS; i += 256) cf[i] = g_coef[i];
    for (int i = tid; i < OUT_DIM * HID; i += 256) wo[i] = wout[i];
    __syncthreads();

    float v0 = 0.f, v1 = 0.f;
    float i0 = 0.f, i1 = 0.f;
    float a0 = 0.f, a1 = 0.f;

    const float* xwp = g_xw + (size_t)e * HID + half * 64 + lane;
    const size_t tstride = (size_t)BATCH * HID;
    const float2* wr2 = (const float2*)wrp;    // column k slice: wr2[k*64 + half*32 + lane]
    unsigned* slot = msk + pair * 8;           // two 16B buffers
    int barid = pair + 1;

    float xn0 = xwp[0], xn1 = xwp[32];

    for (int t = 0; t < T_STEPS; ++t) {
        float xc0 = xn0, xc1 = xn1;
        if (t + 1 < T_STEPS) {
            const float* p = xwp + (size_t)(t + 1) * tstride;
            xn0 = p[0]; xn1 = p[32];
        }
        float ct = cf[t];

        // identical op forms/order to R2
        float vd0 = __fadd_rn(v0, __fmul_rn(0.1f, __fadd_rn(__fsub_rn(0.f, v0), i0)));
        float vd1 = __fadd_rn(v1, __fmul_rn(0.1f, __fadd_rn(__fsub_rn(0.f, v1), i1)));
        float id0 = __fsub_rn(i0, __fmul_rn(0.2f, i0));
        float id1 = __fsub_rn(i1, __fmul_rn(0.2f, i1));
        bool z0 = __fsub_rn(vd0, 1.0f) > 0.0f;
        bool z1 = __fsub_rn(vd1, 1.0f) > 0.0f;
        v0 = z0 ? 0.0f : vd0;
        v1 = z1 ? 0.0f : vd1;
        if (z0) a0 = __fadd_rn(a0, ct);
        if (z1) a1 = __fadd_rn(a1, ct);

        unsigned mA = __ballot_sync(0xffffffffu, z0);  // k range half*64 +[0,32)
        unsigned mB = __ballot_sync(0xffffffffu, z1);  // k range half*64 +[32,64)

        // exchange masks (double-buffered; bar orders STS before LDS)
        unsigned* buf = slot + (t & 1) * 4;
        if (lane == 0) {
            unsigned long long pk = (unsigned long long)mA |
                                    ((unsigned long long)mB << 32);
            *(unsigned long long*)(buf + half * 2) = pk;
        }
        asm volatile("bar.sync %0, 64;" :: "r"(barid) : "memory");
        uint4 allm = *(const uint4*)buf;   // masks for k 0-31,32-63,64-95,96-127

        // drain ascending k; packed f32x2 adds (independent halves, bitwise)
        unsigned long long Rp = 0ull;      // (+0.0f, +0.0f)
        unsigned mm;
        mm = allm.x;
        while (mm) {
            int k = __ffs((int)mm) - 1; mm &= mm - 1;
            unsigned long long q = *(const unsigned long long*)&wr2[k * 64 + half * 32 + lane];
            asm("add.rn.f32x2 %0, %0, %1;" : "+l"(Rp) : "l"(q));
        }
        mm = allm.y;
        while (mm) {
            int k = 32 + __ffs((int)mm) - 1; mm &= mm - 1;
            unsigned long long q = *(const unsigned long long*)&wr2[k * 64 + half * 32 + lane];
            asm("add.rn.f32x2 %0, %0, %1;" : "+l"(Rp) : "l"(q));
        }
        mm = allm.z;
        while (mm) {
            int k = 64 + __ffs((int)mm) - 1; mm &= mm - 1;
            unsigned long long q = *(const unsigned long long*)&wr2[k * 64 + half * 32 + lane];
            asm("add.rn.f32x2 %0, %0, %1;" : "+l"(Rp) : "l"(q));
        }
        mm = allm.w;
        while (mm) {
            int k = 96 + __ffs((int)mm) - 1; mm &= mm - 1;
            unsigned long long q = *(const unsigned long long*)&wr2[k * 64 + half * 32 + lane];
            asm("add.rn.f32x2 %0, %0, %1;" : "+l"(Rp) : "l"(q));
        }
        float R0, R1;
        asm("mov.b64 {%0, %1}, %2;" : "=f"(R0), "=f"(R1) : "l"(Rp));

        i0 = __fadd_rn(__fadd_rn(id0, xc0), R0);
        i1 = __fadd_rn(__fadd_rn(id1, xc1), R1);
    }

    // Readout partials: this warp covers h = half*64 + {lane, 32+lane}
#pragma unroll
    for (int o = 0; o < OUT_DIM; ++o) {
        const float* wp = &wo[o * HID + half * 64];
        float p = a0 * wp[lane] + a1 * wp[32 + lane];
#pragma unroll
        for (int s = 16; s; s >>= 1) p += __shfl_xor_sync(0xffffffffu, p, s);
        if (lane == 0) part[wid * OUT_DIM + o] = p;
    }
    __syncthreads();
    if (half == 0 && lane == 0) {
        float vo[OUT_DIM];
#pragma unroll
        for (int o = 0; o < OUT_DIM; ++o)
            vo[o] = part[wid * OUT_DIM + o] + part[(wid + 1) * OUT_DIM + o];
        float mx = vo[0];
#pragma unroll
        for (int o = 1; o < OUT_DIM; ++o) mx = fmaxf(mx, vo[o]);
        float se = 0.f;
#pragma unroll
        for (int o = 0; o < OUT_DIM; ++o) se += expf(vo[o] - mx);
        float lse = mx + logf(se);
#pragma unroll
        for (int o = 0; o < OUT_DIM; ++o) out[e * OUT_DIM + o] = vo[o] - lse;
    }
}

extern "C" void kernel_launch(void* const* d_in, const int* in_sizes, int n_in,
                              void* d_out, int out_size) {
    const float* x     = (const float*)d_in[0];
    const float* w_in  = (const float*)d_in[1];
    const float* w_rec = (const float*)d_in[2];
    const float* w_out = (const float*)d_in[3];
    float* out = (float*)d_out;

    cudaFuncSetAttribute(gemm_in, cudaFuncAttributeMaxDynamicSharedMemorySize,
                         GEMM_SMEM);
    cudaFuncSetAttribute(sim_kernel, cudaFuncAttributeMaxDynamicSharedMemorySize,
                         SIM_SMEM);

    prep_kernel<<<64, 256>>>(w_rec);
    gemm_in<<<(T_STEPS * BATCH) / 128, 256, GEMM_SMEM>>>(x, w_in);
    sim_kernel<<<BATCH / 4, 256, SIM_SMEM>>>(w_out, out);
}